// round 13
// baseline (speedup 1.0000x reference)
#include <cuda_runtime.h>
#include <cuda_fp16.h>
#include <cuda_bf16.h>
#include <mma.h>
#include <math.h>
#include <cstdint>

#define BATCH   2
#define SEQ     2048
#define DMODEL  2048
#define HEADS   16
#define DKH     128
#define MROWS   (BATCH*SEQ)

// ---------------- scratch (__device__ globals; allocation-free rule) -------
__device__ __half g_Qh[BATCH*HEADS*SEQ*DKH];
__device__ __half g_Kh[BATCH*HEADS*SEQ*DKH];
__device__ __half g_Vh[BATCH*HEADS*SEQ*DKH];
__device__ __half g_xh [MROWS*DMODEL];
__device__ __half g_wqh[DMODEL*DMODEL];
__device__ __half g_wkh[DMODEL*DMODEL];
__device__ __half g_wvh[DMODEL*DMODEL];
__device__ __half g_woh[DMODEL*DMODEL];
__device__ __half g_aoh[MROWS*DMODEL];

// ---------------------------------------------------------------------------
__global__ void f32_to_f16(const float* __restrict__ in, __half* __restrict__ out, int n4)
{
    int i = blockIdx.x * blockDim.x + threadIdx.x;
    if (i >= n4) return;
    float4 v = *(const float4*)(in + (size_t)i*4);
    *(__half2*)(out + (size_t)i*4)     = __floats2half2_rn(v.x, v.y);
    *(__half2*)(out + (size_t)i*4 + 2) = __floats2half2_rn(v.z, v.w);
}

__global__ void w_to_f16(const float* __restrict__ w0, const float* __restrict__ w1,
                         const float* __restrict__ w2, const float* __restrict__ w3,
                         __half* __restrict__ o0, __half* __restrict__ o1,
                         __half* __restrict__ o2, __half* __restrict__ o3, int n4)
{
    const float* in;
    __half* out;
    switch (blockIdx.y) {
        case 0: in = w0; out = o0; break;
        case 1: in = w1; out = o1; break;
        case 2: in = w2; out = o2; break;
        default: in = w3; out = o3; break;
    }
    int i = blockIdx.x * blockDim.x + threadIdx.x;
    if (i >= n4) return;
    float4 v = *(const float4*)(in + (size_t)i*4);
    *(__half2*)(out + (size_t)i*4)     = __floats2half2_rn(v.x, v.y);
    *(__half2*)(out + (size_t)i*4 + 2) = __floats2half2_rn(v.z, v.w);
}

// ---------------------------------------------------------------------------
__device__ __forceinline__ void cp_async16(void* smem, const void* gmem)
{
    unsigned int s = (unsigned int)__cvta_generic_to_shared(smem);
    asm volatile("cp.async.cg.shared.global [%0], [%1], 16;\n" :: "r"(s), "l"(gmem));
}
__device__ __forceinline__ void cp_commit() { asm volatile("cp.async.commit_group;\n"); }
template<int N> __device__ __forceinline__ void cp_wait() { asm volatile("cp.async.wait_group %0;\n" :: "n"(N)); }

__device__ __forceinline__ unsigned int smaddr(const void* p)
{ return (unsigned int)__cvta_generic_to_shared(p); }

__device__ __forceinline__ void ldsm4(uint32_t* r, unsigned int a)
{
    asm volatile("ldmatrix.sync.aligned.m8n8.x4.shared.b16 {%0,%1,%2,%3}, [%4];"
                 : "=r"(r[0]), "=r"(r[1]), "=r"(r[2]), "=r"(r[3]) : "r"(a));
}
__device__ __forceinline__ void ldsm4t(uint32_t* r, unsigned int a)
{
    asm volatile("ldmatrix.sync.aligned.m8n8.x4.trans.shared.b16 {%0,%1,%2,%3}, [%4];"
                 : "=r"(r[0]), "=r"(r[1]), "=r"(r[2]), "=r"(r[3]) : "r"(a));
}
__device__ __forceinline__ void mma16816(float* d, const uint32_t* a, const uint32_t* b)
{
    asm volatile("mma.sync.aligned.m16n8k16.row.col.f32.f16.f16.f32 "
                 "{%0,%1,%2,%3},{%4,%5,%6,%7},{%8,%9},{%0,%1,%2,%3};"
                 : "+f"(d[0]), "+f"(d[1]), "+f"(d[2]), "+f"(d[3])
                 : "r"(a[0]), "r"(a[1]), "r"(a[2]), "r"(a[3]), "r"(b[0]), "r"(b[1]));
}

#define BARSYNC(id, n)   asm volatile("bar.sync %0, %1;"   :: "r"(id), "r"(n) : "memory")
#define BARARRIVE(id, n) asm volatile("bar.arrive %0, %1;" :: "r"(id), "r"(n) : "memory")

// ---------------------------------------------------------------------------
// Raw-mma fp16 GEMM, 128x128 CTA tile, 32x64 warp tile (4m x 2n warps).
// GBK=64, 3-stage cp.async. ldsm/MMA ratio 2.67 (was 1.33).
// ---------------------------------------------------------------------------
#define GSTAGES 3
#define GBK     64
#define GAP     72
#define GSTAGE_HALVES (2*128*GAP)
#define GEMM_SMEM_BYTES (GSTAGES*GSTAGE_HALVES*(int)sizeof(__half))

template<bool QKV>
__global__ __launch_bounds__(256, 2)
void gemm_raw(const __half* __restrict__ A,
              const __half* __restrict__ W0, const __half* __restrict__ W1, const __half* __restrict__ W2,
              float* __restrict__ C0,
              __half* __restrict__ H0, __half* __restrict__ H1, __half* __restrict__ H2)
{
    extern __shared__ __half sm_h[];

    const __half* W = W0;
    if (QKV) {
        if (blockIdx.z == 1) W = W1;
        else if (blockIdx.z == 2) W = W2;
    }

    const int m0   = blockIdx.y * 128;
    const int n0   = blockIdx.x * 128;
    const int tid  = threadIdx.x;
    const int lane = tid & 31;
    const int wid  = tid >> 5;
    const int wm   = wid & 3;        // 4 warp rows of 32
    const int wn   = wid >> 2;       // 2 warp cols of 64
    const int g    = lane >> 2;
    const int t4   = lane & 3;
    const int l8   = lane & 7;

    float acc[2][8][4];              // [mi(16-row)][ni(8-col)][quad]
#pragma unroll
    for (int mi = 0; mi < 2; mi++)
#pragma unroll
        for (int ni = 0; ni < 8; ni++)
#pragma unroll
            for (int j = 0; j < 4; j++) acc[mi][ni][j] = 0.0f;

    const int NT = 2048 / GBK;       // 32

    auto load_stage = [&](int kt, int buf) {
        __half* sA = sm_h + buf * GSTAGE_HALVES;
        __half* sB = sA + 128*GAP;
        const int kbase = kt * GBK;
#pragma unroll
        for (int it = 0; it < 4; it++) {
            int idx = it*256 + tid;
            int row = idx >> 3, cc = idx & 7;
            cp_async16(&sA[row*GAP + cc*8], A + (size_t)(m0+row)*2048 + kbase + cc*8);
        }
#pragma unroll
        for (int it = 0; it < 4; it++) {
            int idx = it*256 + tid;
            int row = idx >> 3, cc = idx & 7;
            cp_async16(&sB[row*GAP + cc*8], W + (size_t)(n0+row)*2048 + kbase + cc*8);
        }
    };

    load_stage(0, 0); cp_commit();
    load_stage(1, 1); cp_commit();

    int buf = 0, nbuf = 2;
    for (int kt = 0; kt < NT; kt++) {
        cp_wait<1>();
        __syncthreads();
        if (kt + 2 < NT) load_stage(kt + 2, nbuf);
        cp_commit();

        __half* sA = sm_h + buf * GSTAGE_HALVES;
        __half* sB = sA + 128*GAP;

#pragma unroll
        for (int ks = 0; ks < 4; ks++) {
            uint32_t af[2][4];
#pragma unroll
            for (int mi = 0; mi < 2; mi++) {
                int row  = wm*32 + mi*16 + ((lane >> 3) & 1)*8 + l8;
                int koff = ks*16 + (lane >> 4)*8;
                ldsm4(af[mi], smaddr(&sA[row*GAP + koff]));
            }
            uint32_t bf[4][4];
#pragma unroll
            for (int ni2 = 0; ni2 < 4; ni2++) {
                int row  = wn*64 + ni2*16 + ((lane >> 4) & 1)*8 + l8;
                int koff = ks*16 + ((lane >> 3) & 1)*8;
                ldsm4(bf[ni2], smaddr(&sB[row*GAP + koff]));
            }
#pragma unroll
            for (int mi = 0; mi < 2; mi++)
#pragma unroll
                for (int ni2 = 0; ni2 < 4; ni2++) {
                    mma16816(acc[mi][ni2*2],     af[mi], bf[ni2]);
                    mma16816(acc[mi][ni2*2 + 1], af[mi], bf[ni2] + 2);
                }
        }
        buf = (buf + 1 == GSTAGES) ? 0 : buf + 1;
        nbuf = (nbuf + 1 == GSTAGES) ? 0 : nbuf + 1;
    }

    if (QKV) {
        const int b  = m0 / SEQ;
        const int s0 = m0 % SEQ;
        const int h  = blockIdx.x;
        const bool rope   = (blockIdx.z < 2);
        const float scale = (blockIdx.z == 0) ? 0.08838834764831845f : 1.0f;
        __half* H = (blockIdx.z == 0) ? H0 : ((blockIdx.z == 1) ? H1 : H2);
        const size_t hb = (size_t)(b*HEADS + h)*SEQ;

#pragma unroll
        for (int mi = 0; mi < 2; mi++) {
            int r1 = wm*32 + mi*16 + g;
#pragma unroll
            for (int ni = 0; ni < 8; ni++) {
                int c = wn*64 + ni*8 + t4*2;
                float x1a = acc[mi][ni][0], x2a = acc[mi][ni][1];
                float x1b = acc[mi][ni][2], x2b = acc[mi][ni][3];
                __half2 o1, o2;
                if (rope) {
                    float freq = exp2f(-13.287712379549449f * ((float)c * (1.0f/128.0f)));
                    float sn, cs;
                    sincosf((float)(s0 + r1) * freq, &sn, &cs);
                    o1 = __floats2half2_rn((x1a*cs - x2a*sn)*scale, (x1a*sn + x2a*cs)*scale);
                    sincosf((float)(s0 + r1 + 8) * freq, &sn, &cs);
                    o2 = __floats2half2_rn((x1b*cs - x2b*sn)*scale, (x1b*sn + x2b*cs)*scale);
                } else {
                    o1 = __floats2half2_rn(x1a, x2a);
                    o2 = __floats2half2_rn(x1b, x2b);
                }
                *(__half2*)(H + (hb + s0 + r1)*DKH + c)     = o1;
                *(__half2*)(H + (hb + s0 + r1 + 8)*DKH + c) = o2;
            }
        }
    } else {
#pragma unroll
        for (int mi = 0; mi < 2; mi++) {
            int r1 = m0 + wm*32 + mi*16 + g;
#pragma unroll
            for (int ni = 0; ni < 8; ni++) {
                int c = n0 + wn*64 + ni*8 + t4*2;
                *(float2*)(C0 + (size_t)r1*DMODEL + c)       = make_float2(acc[mi][ni][0], acc[mi][ni][1]);
                *(float2*)(C0 + (size_t)(r1 + 8)*DMODEL + c) = make_float2(acc[mi][ni][2], acc[mi][ni][3]);
            }
        }
    }
}

// ---------------------------------------------------------------------------
// Warp-specialized flash attention (causal) — unchanged from R12.
// ---------------------------------------------------------------------------
#define FBR 64
#define FBC 64
#define FDP 136
#define FPP 72
#define FK0 0
#define FK1 8704
#define FV0 17408
#define FV1 26112
#define FP0 34816
#define FP1 39424
#define FHALVES 44032
#define FWS_SMEM (FHALVES*2 + 192*4)

__global__ __launch_bounds__(256, 2)
void flash_ws(const __half* __restrict__ Q, const __half* __restrict__ K,
              const __half* __restrict__ V, __half* __restrict__ AO)
{
    extern __shared__ __half smf[];
    float* alpha0 = (float*)((char*)smf + FHALVES*2);
    float* alpha1 = alpha0 + 64;
    float* lrow   = alpha1 + 64;

    const int qt  = (gridDim.x - 1) - blockIdx.x;
    const int bh  = blockIdx.y;
    const int q0  = qt * FBR;
    const int tid  = threadIdx.x;
    const int lane = tid & 31;
    const int wid  = tid >> 5;
    const int g    = lane >> 2;
    const int t4   = lane & 3;
    const int l8   = lane & 7;
    const int nt   = qt + 1;
    const bool isS = (wid < 4);
    const int  w   = isS ? wid : (wid - 4);
    const int ctid = tid & 127;

    const __half* Qg = Q + ((size_t)bh*SEQ + q0)*DKH;
#pragma unroll
    for (int it = 0; it < 4; it++) {
        int i = it*256 + tid;
        int r = i >> 4, c = i & 15;
        cp_async16(&smf[FP0 + r*FDP + c*8], Qg + (size_t)r*DKH + c*8);
    }
    cp_commit();

    if (isS) {
        const __half* Kg = K + ((size_t)bh*SEQ)*DKH;
#pragma unroll
        for (int it = 0; it < 8; it++) {
            int i = it*128 + ctid;
            int r = i >> 4, c = i & 15;
            cp_async16(&smf[FK0 + r*FDP + c*8], Kg + (size_t)r*DKH + c*8);
        }
    } else {
        const __half* Vg = V + ((size_t)bh*SEQ)*DKH;
#pragma unroll
        for (int it = 0; it < 8; it++) {
            int i = it*128 + ctid;
            int r = i >> 4, c = i & 15;
            cp_async16(&smf[FV0 + r*FDP + c*8], Vg + (size_t)r*DKH + c*8);
        }
    }
    cp_commit();
    cp_wait<1>();
    __syncthreads();

    uint32_t qf[8][4];
    if (isS) {
        int row  = w*16 + ((lane >> 3) & 1)*8 + l8;
        int koff = (lane >> 4) * 8;
#pragma unroll
        for (int ks = 0; ks < 8; ks++)
            ldsm4(qf[ks], smaddr(&smf[FP0 + row*FDP + ks*16 + koff]));
    }
    __syncthreads();

    if (isS) {
        float m1 = -1e30f, m2 = -1e30f, l1 = 0.0f, l2 = 0.0f;
        for (int t = 0; t < nt; t++) {
            if (t + 1 < nt) {
                const __half* Kg = K + ((size_t)bh*SEQ + (size_t)(t+1)*FBC)*DKH;
                __half* kb = &smf[((t+1) & 1) ? FK1 : FK0];
#pragma unroll
                for (int it = 0; it < 8; it++) {
                    int i = it*128 + ctid;
                    int r = i >> 4, c = i & 15;
                    cp_async16(&kb[r*FDP + c*8], Kg + (size_t)r*DKH + c*8);
                }
                cp_commit();
                cp_wait<1>();
            } else cp_wait<0>();
            BARSYNC(5, 128);

            __half* sk = &smf[(t & 1) ? FK1 : FK0];
            float s[8][4];
#pragma unroll
            for (int i = 0; i < 8; i++)
#pragma unroll
                for (int j = 0; j < 4; j++) s[i][j] = 0.0f;

#pragma unroll
            for (int ks = 0; ks < 8; ks++) {
#pragma unroll
                for (int nb2 = 0; nb2 < 4; nb2++) {
                    uint32_t kf[4];
                    int row  = nb2*16 + ((lane >> 4) & 1)*8 + l8;
                    int koff = ks*16 + ((lane >> 3) & 1)*8;
                    ldsm4(kf, smaddr(&sk[row*FDP + koff]));
                    mma16816(s[nb2*2],     qf[ks], kf);
                    mma16816(s[nb2*2 + 1], qf[ks], kf + 2);
                }
            }

            if (t == nt - 1) {
                int row1 = q0 + w*16 + g;
                int row2 = row1 + 8;
                int cb   = t*FBC + t4*2;
#pragma unroll
                for (int nb = 0; nb < 8; nb++) {
                    int c0 = cb + nb*8, c1 = c0 + 1;
                    if (c0 > row1) s[nb][0] = -1e30f;
                    if (c1 > row1) s[nb][1] = -1e30f;
                    if (c0 > row2) s[nb][2] = -1e30f;
                    if (c1 > row2) s[nb][3] = -1e30f;
                }
            }

            float mx1 = -1e30f, mx2 = -1e30f;
#pragma unroll
            for (int nb = 0; nb < 8; nb++) {
                mx1 = fmaxf(mx1, fmaxf(s[nb][0], s[nb][1]));
                mx2 = fmaxf(mx2, fmaxf(s[nb][2], s[nb][3]));
            }
            mx1 = fmaxf(mx1, __shfl_xor_sync(0xffffffffu, mx1, 1));
            mx1 = fmaxf(mx1, __shfl_xor_sync(0xffffffffu, mx1, 2));
            mx2 = fmaxf(mx2, __shfl_xor_sync(0xffffffffu, mx2, 1));
            mx2 = fmaxf(mx2, __shfl_xor_sync(0xffffffffu, mx2, 2));

            float m1n = fmaxf(m1, mx1);
            float m2n = fmaxf(m2, mx2);
            float a1  = __expf(m1 - m1n);
            float a2  = __expf(m2 - m2n);

            float ls1 = 0.0f, ls2 = 0.0f;
            __half2 pp1[8], pp2[8];
#pragma unroll
            for (int nb = 0; nb < 8; nb++) {
                float p0 = __expf(s[nb][0] - m1n);
                float p1 = __expf(s[nb][1] - m1n);
                float p2 = __expf(s[nb][2] - m2n);
                float p3 = __expf(s[nb][3] - m2n);
                ls1 += p0 + p1;
                ls2 += p2 + p3;
                pp1[nb] = __floats2half2_rn(p0, p1);
                pp2[nb] = __floats2half2_rn(p2, p3);
            }
            ls1 += __shfl_xor_sync(0xffffffffu, ls1, 1);
            ls1 += __shfl_xor_sync(0xffffffffu, ls1, 2);
            ls2 += __shfl_xor_sync(0xffffffffu, ls2, 1);
            ls2 += __shfl_xor_sync(0xffffffffu, ls2, 2);

            l1 = l1*a1 + ls1;
            l2 = l2*a2 + ls2;
            m1 = m1n; m2 = m2n;

            if (t >= 2) BARSYNC(3 + (t & 1), 256);

            __half* pb = &smf[(t & 1) ? FP1 : FP0];
            float*  ab = (t & 1) ? alpha1 : alpha0;
            int r1o = (w*16 + g)*FPP;
            int r2o = r1o + 8*FPP;
#pragma unroll
            for (int nb = 0; nb < 8; nb++) {
                *(__half2*)&pb[r1o + nb*8 + t4*2] = pp1[nb];
                *(__half2*)&pb[r2o + nb*8 + t4*2] = pp2[nb];
            }
            if (t4 == 0) {
                ab[w*16 + g]     = a1;
                ab[w*16 + g + 8] = a2;
            }
            BARARRIVE(1 + (t & 1), 256);
            BARSYNC(5, 128);
        }
        if (t4 == 0) {
            lrow[w*16 + g]     = l1;
            lrow[w*16 + g + 8] = l2;
        }
    } else {
        float o[4][4][4];
#pragma unroll
        for (int mi = 0; mi < 4; mi++)
#pragma unroll
            for (int ni = 0; ni < 4; ni++)
#pragma unroll
                for (int j = 0; j < 4; j++) o[mi][ni][j] = 0.0f;

        for (int t = 0; t < nt; t++) {
            if (t + 1 < nt) {
                const __half* Vg = V + ((size_t)bh*SEQ + (size_t)(t+1)*FBC)*DKH;
                __half* vb = &smf[((t+1) & 1) ? FV1 : FV0];
#pragma unroll
                for (int it = 0; it < 8; it++) {
                    int i = it*128 + ctid;
                    int r = i >> 4, c = i & 15;
                    cp_async16(&vb[r*FDP + c*8], Vg + (size_t)r*DKH + c*8);
                }
                cp_commit();
                cp_wait<1>();
            } else cp_wait<0>();
            BARSYNC(6, 128);
            BARSYNC(1 + (t & 1), 256);

            float* ab = (t & 1) ? alpha1 : alpha0;
#pragma unroll
            for (int mi = 0; mi < 4; mi++) {
                float a1 = ab[mi*16 + g];
                float a2 = ab[mi*16 + g + 8];
#pragma unroll
                for (int ni = 0; ni < 4; ni++) {
                    o[mi][ni][0] *= a1; o[mi][ni][1] *= a1;
                    o[mi][ni][2] *= a2; o[mi][ni][3] *= a2;
                }
            }

            __half* pb = &smf[(t & 1) ? FP1 : FP0];
            __half* sv = &smf[(t & 1) ? FV1 : FV0];

            uint32_t vf[4][2][4];
#pragma unroll
            for (int ks = 0; ks < 4; ks++)
#pragma unroll
                for (int nb = 0; nb < 2; nb++) {
                    int vrow = ks*16 + ((lane >> 3) & 1)*8 + l8;
                    int vcol = w*32 + nb*16 + (lane >> 4)*8;
                    ldsm4t(vf[ks][nb], smaddr(&sv[vrow*FDP + vcol]));
                }

#pragma unroll
            for (int ks = 0; ks < 4; ks++) {
#pragma unroll
                for (int mi = 0; mi < 4; mi++) {
                    uint32_t pf[4];
                    int prow = mi*16 + ((lane >> 3) & 1)*8 + l8;
                    int pcol = ks*16 + (lane >> 4)*8;
                    ldsm4(pf, smaddr(&pb[prow*FPP + pcol]));
#pragma unroll
                    for (int nb = 0; nb < 2; nb++) {
                        mma16816(o[mi][nb*2],     pf, vf[ks][nb]);
                        mma16816(o[mi][nb*2 + 1], pf, vf[ks][nb] + 2);
                    }
                }
            }

            if (t + 2 < nt) BARARRIVE(3 + (t & 1), 256);
            BARSYNC(6, 128);
        }

        __syncthreads();
        const int b = bh >> 4;
        const int h = bh & 15;
#pragma unroll
        for (int mi = 0; mi < 4; mi++) {
            int row1 = q0 + mi*16 + g;
            int row2 = row1 + 8;
            float il1 = 1.0f / lrow[mi*16 + g];
            float il2 = 1.0f / lrow[mi*16 + g + 8];
            __half* base1 = AO + ((size_t)(b*SEQ + row1))*DMODEL + h*DKH;
            __half* base2 = AO + ((size_t)(b*SEQ + row2))*DMODEL + h*DKH;
#pragma unroll
            for (int ni = 0; ni < 4; ni++) {
                int col = w*32 + ni*8 + t4*2;
                *(__half2*)(base1 + col) = __floats2half2_rn(o[mi][ni][0]*il1, o[mi][ni][1]*il1);
                *(__half2*)(base2 + col) = __floats2half2_rn(o[mi][ni][2]*il2, o[mi][ni][3]*il2);
            }
        }
        return;
    }
    __syncthreads();
}

// ---------------------------------------------------------------------------
extern "C" void kernel_launch(void* const* d_in, const int* in_sizes, int n_in,
                              void* d_out, int out_size)
{
    const float* x  = (const float*)d_in[0];
    const float* wq = (const float*)d_in[2];
    const float* wk = (const float*)d_in[3];
    const float* wv = (const float*)d_in[4];
    const float* wo = (const float*)d_in[5];
    float* out = (float*)d_out;

    __half *qh, *kh, *vh, *xh, *wqh, *wkh, *wvh, *woh, *aoh;
    cudaGetSymbolAddress((void**)&qh,  g_Qh);
    cudaGetSymbolAddress((void**)&kh,  g_Kh);
    cudaGetSymbolAddress((void**)&vh,  g_Vh);
    cudaGetSymbolAddress((void**)&xh,  g_xh);
    cudaGetSymbolAddress((void**)&wqh, g_wqh);
    cudaGetSymbolAddress((void**)&wkh, g_wkh);
    cudaGetSymbolAddress((void**)&wvh, g_wvh);
    cudaGetSymbolAddress((void**)&woh, g_woh);
    cudaGetSymbolAddress((void**)&aoh, g_aoh);

    cudaFuncSetAttribute(gemm_raw<true>,  cudaFuncAttributeMaxDynamicSharedMemorySize, GEMM_SMEM_BYTES);
    cudaFuncSetAttribute(gemm_raw<false>, cudaFuncAttributeMaxDynamicSharedMemorySize, GEMM_SMEM_BYTES);
    cudaFuncSetAttribute(flash_ws, cudaFuncAttributeMaxDynamicSharedMemorySize, FWS_SMEM);

    {
        int n4x = MROWS*DMODEL/4;
        int n4w = DMODEL*DMODEL/4;
        f32_to_f16<<<(n4x+255)/256, 256>>>(x, xh, n4x);
        dim3 wgrid((n4w+255)/256, 4);
        w_to_f16<<<wgrid, 256>>>(wq, wk, wv, wo, wqh, wkh, wvh, woh, n4w);
    }

    dim3 qkv_grid(DMODEL/128, MROWS/128, 3);
    gemm_raw<true><<<qkv_grid, 256, GEMM_SMEM_BYTES>>>(xh, wqh, wkh, wvh,
                                                       nullptr, qh, kh, vh);

    dim3 fgrid(SEQ/FBR, BATCH*HEADS);
    flash_ws<<<fgrid, 256, FWS_SMEM>>>(qh, kh, vh, aoh);

    dim3 wo_grid(DMODEL/128, MROWS/128, 1);
    gemm_raw<false><<<wo_grid, 256, GEMM_SMEM_BYTES>>>(aoh, woh, nullptr, nullptr,
                                                       out, nullptr, nullptr, nullptr);
}

// round 14
// speedup vs baseline: 1.0401x; 1.0401x over previous
#include <cuda_runtime.h>
#include <cuda_fp16.h>
#include <cuda_bf16.h>
#include <mma.h>
#include <math.h>
#include <cstdint>

#define BATCH   2
#define SEQ     2048
#define DMODEL  2048
#define HEADS   16
#define DKH     128
#define MROWS   (BATCH*SEQ)

// ---------------- scratch (__device__ globals; allocation-free rule) -------
__device__ __half g_Qh[BATCH*HEADS*SEQ*DKH];
__device__ __half g_Kh[BATCH*HEADS*SEQ*DKH];
__device__ __half g_Vh[BATCH*HEADS*SEQ*DKH];
__device__ __half g_xh [MROWS*DMODEL];
__device__ __half g_wqh[DMODEL*DMODEL];
__device__ __half g_wkh[DMODEL*DMODEL];
__device__ __half g_wvh[DMODEL*DMODEL];
__device__ __half g_woh[DMODEL*DMODEL];
__device__ __half g_aoh[MROWS*DMODEL];

// ---------------------------------------------------------------------------
// All 5 fp32->fp16 converts in ONE launch; 4 independent float4s per thread
// (MLP=4 hides DRAM latency; was MLP=1 at 30% of HBM peak).
// ---------------------------------------------------------------------------
#define CVT_N4X (MROWS*DMODEL/4)     // 2M float4 for x
#define CVT_N4W (DMODEL*DMODEL/4)    // 1M float4 per weight
#define CVT_TPB 256
#define CVT_PER_THREAD 4
#define CVT_BLOCKS ((CVT_N4X + CVT_TPB*CVT_PER_THREAD - 1) / (CVT_TPB*CVT_PER_THREAD))

__global__ void convert_all(const float* __restrict__ x,
                            const float* __restrict__ w0, const float* __restrict__ w1,
                            const float* __restrict__ w2, const float* __restrict__ w3,
                            __half* __restrict__ xo,
                            __half* __restrict__ o0, __half* __restrict__ o1,
                            __half* __restrict__ o2, __half* __restrict__ o3)
{
    const float* in;
    __half* out;
    int n4;
    switch (blockIdx.y) {
        case 0: in = x;  out = xo; n4 = CVT_N4X; break;
        case 1: in = w0; out = o0; n4 = CVT_N4W; break;
        case 2: in = w1; out = o1; n4 = CVT_N4W; break;
        case 3: in = w2; out = o2; n4 = CVT_N4W; break;
        default: in = w3; out = o3; n4 = CVT_N4W; break;
    }
    const int total = gridDim.x * CVT_TPB;
    const int base  = blockIdx.x * CVT_TPB + threadIdx.x;

    float4 v[CVT_PER_THREAD];
    int idx[CVT_PER_THREAD];
    bool ok[CVT_PER_THREAD];
#pragma unroll
    for (int j = 0; j < CVT_PER_THREAD; j++) {
        idx[j] = base + j*total;
        ok[j]  = idx[j] < n4;
        if (ok[j]) v[j] = *(const float4*)(in + (size_t)idx[j]*4);
    }
#pragma unroll
    for (int j = 0; j < CVT_PER_THREAD; j++) {
        if (ok[j]) {
            *(__half2*)(out + (size_t)idx[j]*4)     = __floats2half2_rn(v[j].x, v[j].y);
            *(__half2*)(out + (size_t)idx[j]*4 + 2) = __floats2half2_rn(v[j].z, v[j].w);
        }
    }
}

// ---------------------------------------------------------------------------
__device__ __forceinline__ void cp_async16(void* smem, const void* gmem)
{
    unsigned int s = (unsigned int)__cvta_generic_to_shared(smem);
    asm volatile("cp.async.cg.shared.global [%0], [%1], 16;\n" :: "r"(s), "l"(gmem));
}
__device__ __forceinline__ void cp_commit() { asm volatile("cp.async.commit_group;\n"); }
template<int N> __device__ __forceinline__ void cp_wait() { asm volatile("cp.async.wait_group %0;\n" :: "n"(N)); }

__device__ __forceinline__ unsigned int smaddr(const void* p)
{ return (unsigned int)__cvta_generic_to_shared(p); }

__device__ __forceinline__ void ldsm4(uint32_t* r, unsigned int a)
{
    asm volatile("ldmatrix.sync.aligned.m8n8.x4.shared.b16 {%0,%1,%2,%3}, [%4];"
                 : "=r"(r[0]), "=r"(r[1]), "=r"(r[2]), "=r"(r[3]) : "r"(a));
}
__device__ __forceinline__ void ldsm4t(uint32_t* r, unsigned int a)
{
    asm volatile("ldmatrix.sync.aligned.m8n8.x4.trans.shared.b16 {%0,%1,%2,%3}, [%4];"
                 : "=r"(r[0]), "=r"(r[1]), "=r"(r[2]), "=r"(r[3]) : "r"(a));
}
__device__ __forceinline__ void mma16816(float* d, const uint32_t* a, const uint32_t* b)
{
    asm volatile("mma.sync.aligned.m16n8k16.row.col.f32.f16.f16.f32 "
                 "{%0,%1,%2,%3},{%4,%5,%6,%7},{%8,%9},{%0,%1,%2,%3};"
                 : "+f"(d[0]), "+f"(d[1]), "+f"(d[2]), "+f"(d[3])
                 : "r"(a[0]), "r"(a[1]), "r"(a[2]), "r"(a[3]), "r"(b[0]), "r"(b[1]));
}

#define BARSYNC(id, n)   asm volatile("bar.sync %0, %1;"   :: "r"(id), "r"(n) : "memory")
#define BARARRIVE(id, n) asm volatile("bar.arrive %0, %1;" :: "r"(id), "r"(n) : "memory")

// ---------------------------------------------------------------------------
// Raw-mma fp16 GEMM — EXACT R12 configuration (measured optimum):
// 128x128 CTA tile, 64x32 warp tile, GBK=64, 3-stage cp.async, 2 CTAs/SM.
// ---------------------------------------------------------------------------
#define GSTAGES 3
#define GBK     64
#define GAP     72
#define GSTAGE_HALVES (2*128*GAP)
#define GEMM_SMEM_BYTES (GSTAGES*GSTAGE_HALVES*(int)sizeof(__half))

template<bool QKV>
__global__ __launch_bounds__(256, 2)
void gemm_raw(const __half* __restrict__ A,
              const __half* __restrict__ W0, const __half* __restrict__ W1, const __half* __restrict__ W2,
              float* __restrict__ C0,
              __half* __restrict__ H0, __half* __restrict__ H1, __half* __restrict__ H2)
{
    extern __shared__ __half sm_h[];

    const __half* W = W0;
    if (QKV) {
        if (blockIdx.z == 1) W = W1;
        else if (blockIdx.z == 2) W = W2;
    }

    const int m0   = blockIdx.y * 128;
    const int n0   = blockIdx.x * 128;
    const int tid  = threadIdx.x;
    const int lane = tid & 31;
    const int wid  = tid >> 5;
    const int wm   = wid & 1;
    const int wn   = wid >> 1;
    const int g    = lane >> 2;
    const int t4   = lane & 3;
    const int l8   = lane & 7;

    float acc[4][4][4];
#pragma unroll
    for (int mi = 0; mi < 4; mi++)
#pragma unroll
        for (int ni = 0; ni < 4; ni++)
#pragma unroll
            for (int j = 0; j < 4; j++) acc[mi][ni][j] = 0.0f;

    const int NT = 2048 / GBK;

    auto load_stage = [&](int kt, int buf) {
        __half* sA = sm_h + buf * GSTAGE_HALVES;
        __half* sB = sA + 128*GAP;
        const int kbase = kt * GBK;
#pragma unroll
        for (int it = 0; it < 4; it++) {
            int idx = it*256 + tid;
            int row = idx >> 3, cc = idx & 7;
            cp_async16(&sA[row*GAP + cc*8], A + (size_t)(m0+row)*2048 + kbase + cc*8);
        }
#pragma unroll
        for (int it = 0; it < 4; it++) {
            int idx = it*256 + tid;
            int row = idx >> 3, cc = idx & 7;
            cp_async16(&sB[row*GAP + cc*8], W + (size_t)(n0+row)*2048 + kbase + cc*8);
        }
    };

    load_stage(0, 0); cp_commit();
    load_stage(1, 1); cp_commit();

    int buf = 0, nbuf = 2;
    for (int kt = 0; kt < NT; kt++) {
        cp_wait<1>();
        __syncthreads();
        if (kt + 2 < NT) load_stage(kt + 2, nbuf);
        cp_commit();

        __half* sA = sm_h + buf * GSTAGE_HALVES;
        __half* sB = sA + 128*GAP;

#pragma unroll
        for (int ks = 0; ks < 4; ks++) {
            uint32_t af[4][4];
#pragma unroll
            for (int mi = 0; mi < 4; mi++) {
                int row  = wm*64 + mi*16 + ((lane >> 3) & 1)*8 + l8;
                int koff = ks*16 + (lane >> 4)*8;
                ldsm4(af[mi], smaddr(&sA[row*GAP + koff]));
            }
            uint32_t bf[2][4];
#pragma unroll
            for (int ni2 = 0; ni2 < 2; ni2++) {
                int row  = wn*32 + ni2*16 + ((lane >> 4) & 1)*8 + l8;
                int koff = ks*16 + ((lane >> 3) & 1)*8;
                ldsm4(bf[ni2], smaddr(&sB[row*GAP + koff]));
            }
#pragma unroll
            for (int mi = 0; mi < 4; mi++)
#pragma unroll
                for (int ni2 = 0; ni2 < 2; ni2++) {
                    mma16816(acc[mi][ni2*2],     af[mi], bf[ni2]);
                    mma16816(acc[mi][ni2*2 + 1], af[mi], bf[ni2] + 2);
                }
        }
        buf = (buf + 1 == GSTAGES) ? 0 : buf + 1;
        nbuf = (nbuf + 1 == GSTAGES) ? 0 : nbuf + 1;
    }

    if (QKV) {
        const int b  = m0 / SEQ;
        const int s0 = m0 % SEQ;
        const int h  = blockIdx.x;
        const bool rope   = (blockIdx.z < 2);
        const float scale = (blockIdx.z == 0) ? 0.08838834764831845f : 1.0f;
        __half* H = (blockIdx.z == 0) ? H0 : ((blockIdx.z == 1) ? H1 : H2);
        const size_t hb = (size_t)(b*HEADS + h)*SEQ;

#pragma unroll
        for (int mi = 0; mi < 4; mi++) {
            int r1 = wm*64 + mi*16 + g;
#pragma unroll
            for (int ni = 0; ni < 4; ni++) {
                int c = wn*32 + ni*8 + t4*2;
                float x1a = acc[mi][ni][0], x2a = acc[mi][ni][1];
                float x1b = acc[mi][ni][2], x2b = acc[mi][ni][3];
                __half2 o1, o2;
                if (rope) {
                    float freq = exp2f(-13.287712379549449f * ((float)c * (1.0f/128.0f)));
                    float sn, cs;
                    sincosf((float)(s0 + r1) * freq, &sn, &cs);
                    o1 = __floats2half2_rn((x1a*cs - x2a*sn)*scale, (x1a*sn + x2a*cs)*scale);
                    sincosf((float)(s0 + r1 + 8) * freq, &sn, &cs);
                    o2 = __floats2half2_rn((x1b*cs - x2b*sn)*scale, (x1b*sn + x2b*cs)*scale);
                } else {
                    o1 = __floats2half2_rn(x1a, x2a);
                    o2 = __floats2half2_rn(x1b, x2b);
                }
                *(__half2*)(H + (hb + s0 + r1)*DKH + c)     = o1;
                *(__half2*)(H + (hb + s0 + r1 + 8)*DKH + c) = o2;
            }
        }
    } else {
#pragma unroll
        for (int mi = 0; mi < 4; mi++) {
            int r1 = m0 + wm*64 + mi*16 + g;
#pragma unroll
            for (int ni = 0; ni < 4; ni++) {
                int c = n0 + wn*32 + ni*8 + t4*2;
                *(float2*)(C0 + (size_t)r1*DMODEL + c)       = make_float2(acc[mi][ni][0], acc[mi][ni][1]);
                *(float2*)(C0 + (size_t)(r1 + 8)*DMODEL + c) = make_float2(acc[mi][ni][2], acc[mi][ni][3]);
            }
        }
    }
}

// ---------------------------------------------------------------------------
// Warp-specialized flash attention (causal) — unchanged (known good).
// ---------------------------------------------------------------------------
#define FBR 64
#define FBC 64
#define FDP 136
#define FPP 72
#define FK0 0
#define FK1 8704
#define FV0 17408
#define FV1 26112
#define FP0 34816
#define FP1 39424
#define FHALVES 44032
#define FWS_SMEM (FHALVES*2 + 192*4)

__global__ __launch_bounds__(256, 2)
void flash_ws(const __half* __restrict__ Q, const __half* __restrict__ K,
              const __half* __restrict__ V, __half* __restrict__ AO)
{
    extern __shared__ __half smf[];
    float* alpha0 = (float*)((char*)smf + FHALVES*2);
    float* alpha1 = alpha0 + 64;
    float* lrow   = alpha1 + 64;

    const int qt  = (gridDim.x - 1) - blockIdx.x;
    const int bh  = blockIdx.y;
    const int q0  = qt * FBR;
    const int tid  = threadIdx.x;
    const int lane = tid & 31;
    const int wid  = tid >> 5;
    const int g    = lane >> 2;
    const int t4   = lane & 3;
    const int l8   = lane & 7;
    const int nt   = qt + 1;
    const bool isS = (wid < 4);
    const int  w   = isS ? wid : (wid - 4);
    const int ctid = tid & 127;

    const __half* Qg = Q + ((size_t)bh*SEQ + q0)*DKH;
#pragma unroll
    for (int it = 0; it < 4; it++) {
        int i = it*256 + tid;
        int r = i >> 4, c = i & 15;
        cp_async16(&smf[FP0 + r*FDP + c*8], Qg + (size_t)r*DKH + c*8);
    }
    cp_commit();

    if (isS) {
        const __half* Kg = K + ((size_t)bh*SEQ)*DKH;
#pragma unroll
        for (int it = 0; it < 8; it++) {
            int i = it*128 + ctid;
            int r = i >> 4, c = i & 15;
            cp_async16(&smf[FK0 + r*FDP + c*8], Kg + (size_t)r*DKH + c*8);
        }
    } else {
        const __half* Vg = V + ((size_t)bh*SEQ)*DKH;
#pragma unroll
        for (int it = 0; it < 8; it++) {
            int i = it*128 + ctid;
            int r = i >> 4, c = i & 15;
            cp_async16(&smf[FV0 + r*FDP + c*8], Vg + (size_t)r*DKH + c*8);
        }
    }
    cp_commit();
    cp_wait<1>();
    __syncthreads();

    uint32_t qf[8][4];
    if (isS) {
        int row  = w*16 + ((lane >> 3) & 1)*8 + l8;
        int koff = (lane >> 4) * 8;
#pragma unroll
        for (int ks = 0; ks < 8; ks++)
            ldsm4(qf[ks], smaddr(&smf[FP0 + row*FDP + ks*16 + koff]));
    }
    __syncthreads();

    if (isS) {
        float m1 = -1e30f, m2 = -1e30f, l1 = 0.0f, l2 = 0.0f;
        for (int t = 0; t < nt; t++) {
            if (t + 1 < nt) {
                const __half* Kg = K + ((size_t)bh*SEQ + (size_t)(t+1)*FBC)*DKH;
                __half* kb = &smf[((t+1) & 1) ? FK1 : FK0];
#pragma unroll
                for (int it = 0; it < 8; it++) {
                    int i = it*128 + ctid;
                    int r = i >> 4, c = i & 15;
                    cp_async16(&kb[r*FDP + c*8], Kg + (size_t)r*DKH + c*8);
                }
                cp_commit();
                cp_wait<1>();
            } else cp_wait<0>();
            BARSYNC(5, 128);

            __half* sk = &smf[(t & 1) ? FK1 : FK0];
            float s[8][4];
#pragma unroll
            for (int i = 0; i < 8; i++)
#pragma unroll
                for (int j = 0; j < 4; j++) s[i][j] = 0.0f;

#pragma unroll
            for (int ks = 0; ks < 8; ks++) {
#pragma unroll
                for (int nb2 = 0; nb2 < 4; nb2++) {
                    uint32_t kf[4];
                    int row  = nb2*16 + ((lane >> 4) & 1)*8 + l8;
                    int koff = ks*16 + ((lane >> 3) & 1)*8;
                    ldsm4(kf, smaddr(&sk[row*FDP + koff]));
                    mma16816(s[nb2*2],     qf[ks], kf);
                    mma16816(s[nb2*2 + 1], qf[ks], kf + 2);
                }
            }

            if (t == nt - 1) {
                int row1 = q0 + w*16 + g;
                int row2 = row1 + 8;
                int cb   = t*FBC + t4*2;
#pragma unroll
                for (int nb = 0; nb < 8; nb++) {
                    int c0 = cb + nb*8, c1 = c0 + 1;
                    if (c0 > row1) s[nb][0] = -1e30f;
                    if (c1 > row1) s[nb][1] = -1e30f;
                    if (c0 > row2) s[nb][2] = -1e30f;
                    if (c1 > row2) s[nb][3] = -1e30f;
                }
            }

            float mx1 = -1e30f, mx2 = -1e30f;
#pragma unroll
            for (int nb = 0; nb < 8; nb++) {
                mx1 = fmaxf(mx1, fmaxf(s[nb][0], s[nb][1]));
                mx2 = fmaxf(mx2, fmaxf(s[nb][2], s[nb][3]));
            }
            mx1 = fmaxf(mx1, __shfl_xor_sync(0xffffffffu, mx1, 1));
            mx1 = fmaxf(mx1, __shfl_xor_sync(0xffffffffu, mx1, 2));
            mx2 = fmaxf(mx2, __shfl_xor_sync(0xffffffffu, mx2, 1));
            mx2 = fmaxf(mx2, __shfl_xor_sync(0xffffffffu, mx2, 2));

            float m1n = fmaxf(m1, mx1);
            float m2n = fmaxf(m2, mx2);
            float a1  = __expf(m1 - m1n);
            float a2  = __expf(m2 - m2n);

            float ls1 = 0.0f, ls2 = 0.0f;
            __half2 pp1[8], pp2[8];
#pragma unroll
            for (int nb = 0; nb < 8; nb++) {
                float p0 = __expf(s[nb][0] - m1n);
                float p1 = __expf(s[nb][1] - m1n);
                float p2 = __expf(s[nb][2] - m2n);
                float p3 = __expf(s[nb][3] - m2n);
                ls1 += p0 + p1;
                ls2 += p2 + p3;
                pp1[nb] = __floats2half2_rn(p0, p1);
                pp2[nb] = __floats2half2_rn(p2, p3);
            }
            ls1 += __shfl_xor_sync(0xffffffffu, ls1, 1);
            ls1 += __shfl_xor_sync(0xffffffffu, ls1, 2);
            ls2 += __shfl_xor_sync(0xffffffffu, ls2, 1);
            ls2 += __shfl_xor_sync(0xffffffffu, ls2, 2);

            l1 = l1*a1 + ls1;
            l2 = l2*a2 + ls2;
            m1 = m1n; m2 = m2n;

            if (t >= 2) BARSYNC(3 + (t & 1), 256);

            __half* pb = &smf[(t & 1) ? FP1 : FP0];
            float*  ab = (t & 1) ? alpha1 : alpha0;
            int r1o = (w*16 + g)*FPP;
            int r2o = r1o + 8*FPP;
#pragma unroll
            for (int nb = 0; nb < 8; nb++) {
                *(__half2*)&pb[r1o + nb*8 + t4*2] = pp1[nb];
                *(__half2*)&pb[r2o + nb*8 + t4*2] = pp2[nb];
            }
            if (t4 == 0) {
                ab[w*16 + g]     = a1;
                ab[w*16 + g + 8] = a2;
            }
            BARARRIVE(1 + (t & 1), 256);
            BARSYNC(5, 128);
        }
        if (t4 == 0) {
            lrow[w*16 + g]     = l1;
            lrow[w*16 + g + 8] = l2;
        }
    } else {
        float o[4][4][4];
#pragma unroll
        for (int mi = 0; mi < 4; mi++)
#pragma unroll
            for (int ni = 0; ni < 4; ni++)
#pragma unroll
                for (int j = 0; j < 4; j++) o[mi][ni][j] = 0.0f;

        for (int t = 0; t < nt; t++) {
            if (t + 1 < nt) {
                const __half* Vg = V + ((size_t)bh*SEQ + (size_t)(t+1)*FBC)*DKH;
                __half* vb = &smf[((t+1) & 1) ? FV1 : FV0];
#pragma unroll
                for (int it = 0; it < 8; it++) {
                    int i = it*128 + ctid;
                    int r = i >> 4, c = i & 15;
                    cp_async16(&vb[r*FDP + c*8], Vg + (size_t)r*DKH + c*8);
                }
                cp_commit();
                cp_wait<1>();
            } else cp_wait<0>();
            BARSYNC(6, 128);
            BARSYNC(1 + (t & 1), 256);

            float* ab = (t & 1) ? alpha1 : alpha0;
#pragma unroll
            for (int mi = 0; mi < 4; mi++) {
                float a1 = ab[mi*16 + g];
                float a2 = ab[mi*16 + g + 8];
#pragma unroll
                for (int ni = 0; ni < 4; ni++) {
                    o[mi][ni][0] *= a1; o[mi][ni][1] *= a1;
                    o[mi][ni][2] *= a2; o[mi][ni][3] *= a2;
                }
            }

            __half* pb = &smf[(t & 1) ? FP1 : FP0];
            __half* sv = &smf[(t & 1) ? FV1 : FV0];

            uint32_t vf[4][2][4];
#pragma unroll
            for (int ks = 0; ks < 4; ks++)
#pragma unroll
                for (int nb = 0; nb < 2; nb++) {
                    int vrow = ks*16 + ((lane >> 3) & 1)*8 + l8;
                    int vcol = w*32 + nb*16 + (lane >> 4)*8;
                    ldsm4t(vf[ks][nb], smaddr(&sv[vrow*FDP + vcol]));
                }

#pragma unroll
            for (int ks = 0; ks < 4; ks++) {
#pragma unroll
                for (int mi = 0; mi < 4; mi++) {
                    uint32_t pf[4];
                    int prow = mi*16 + ((lane >> 3) & 1)*8 + l8;
                    int pcol = ks*16 + (lane >> 4)*8;
                    ldsm4(pf, smaddr(&pb[prow*FPP + pcol]));
#pragma unroll
                    for (int nb = 0; nb < 2; nb++) {
                        mma16816(o[mi][nb*2],     pf, vf[ks][nb]);
                        mma16816(o[mi][nb*2 + 1], pf, vf[ks][nb] + 2);
                    }
                }
            }

            if (t + 2 < nt) BARARRIVE(3 + (t & 1), 256);
            BARSYNC(6, 128);
        }

        __syncthreads();
        const int b = bh >> 4;
        const int h = bh & 15;
#pragma unroll
        for (int mi = 0; mi < 4; mi++) {
            int row1 = q0 + mi*16 + g;
            int row2 = row1 + 8;
            float il1 = 1.0f / lrow[mi*16 + g];
            float il2 = 1.0f / lrow[mi*16 + g + 8];
            __half* base1 = AO + ((size_t)(b*SEQ + row1))*DMODEL + h*DKH;
            __half* base2 = AO + ((size_t)(b*SEQ + row2))*DMODEL + h*DKH;
#pragma unroll
            for (int ni = 0; ni < 4; ni++) {
                int col = w*32 + ni*8 + t4*2;
                *(__half2*)(base1 + col) = __floats2half2_rn(o[mi][ni][0]*il1, o[mi][ni][1]*il1);
                *(__half2*)(base2 + col) = __floats2half2_rn(o[mi][ni][2]*il2, o[mi][ni][3]*il2);
            }
        }
        return;
    }
    __syncthreads();
}

// ---------------------------------------------------------------------------
extern "C" void kernel_launch(void* const* d_in, const int* in_sizes, int n_in,
                              void* d_out, int out_size)
{
    const float* x  = (const float*)d_in[0];
    const float* wq = (const float*)d_in[2];
    const float* wk = (const float*)d_in[3];
    const float* wv = (const float*)d_in[4];
    const float* wo = (const float*)d_in[5];
    float* out = (float*)d_out;

    __half *qh, *kh, *vh, *xh, *wqh, *wkh, *wvh, *woh, *aoh;
    cudaGetSymbolAddress((void**)&qh,  g_Qh);
    cudaGetSymbolAddress((void**)&kh,  g_Kh);
    cudaGetSymbolAddress((void**)&vh,  g_Vh);
    cudaGetSymbolAddress((void**)&xh,  g_xh);
    cudaGetSymbolAddress((void**)&wqh, g_wqh);
    cudaGetSymbolAddress((void**)&wkh, g_wkh);
    cudaGetSymbolAddress((void**)&wvh, g_wvh);
    cudaGetSymbolAddress((void**)&woh, g_woh);
    cudaGetSymbolAddress((void**)&aoh, g_aoh);

    cudaFuncSetAttribute(gemm_raw<true>,  cudaFuncAttributeMaxDynamicSharedMemorySize, GEMM_SMEM_BYTES);
    cudaFuncSetAttribute(gemm_raw<false>, cudaFuncAttributeMaxDynamicSharedMemorySize, GEMM_SMEM_BYTES);
    cudaFuncSetAttribute(flash_ws, cudaFuncAttributeMaxDynamicSharedMemorySize, FWS_SMEM);

    // all converts in one launch (MLP=4 per thread)
    {
        dim3 cgrid(CVT_BLOCKS, 5);
        convert_all<<<cgrid, CVT_TPB>>>(x, wq, wk, wv, wo, xh, wqh, wkh, wvh, woh);
    }

    dim3 qkv_grid(DMODEL/128, MROWS/128, 3);
    gemm_raw<true><<<qkv_grid, 256, GEMM_SMEM_BYTES>>>(xh, wqh, wkh, wvh,
                                                       nullptr, qh, kh, vh);

    dim3 fgrid(SEQ/FBR, BATCH*HEADS);
    flash_ws<<<fgrid, 256, FWS_SMEM>>>(qh, kh, vh, aoh);

    dim3 wo_grid(DMODEL/128, MROWS/128, 1);
    gemm_raw<false><<<wo_grid, 256, GEMM_SMEM_BYTES>>>(aoh, woh, nullptr, nullptr,
                                                       out, nullptr, nullptr, nullptr);
}